// round 6
// baseline (speedup 1.0000x reference)
#include <cuda_runtime.h>
#include <cstdint>

// Spike-latency encoder:
//   trace:  [B=1024, F=128] f32,  center: [C=8] f32
//   out:    [T=100, B=1024, N=1024] f32 one-hot along T per (b,n)
//
// Two-phase: (1) compute all 1M bins once -> packed uint8 scratch (1MB,
// L2-resident); (2) pure write-stream kernel with a trivial prologue
// (one 32-bit L2-hit load), t split 20 ways for max store concurrency.

#define BB 1024
#define FF 128
#define CC 8
#define NN 1024
#define TT 100
#define NCH 20          // t-chunks
#define TCH 5           // t-slabs per chunk

// bins[b*NN + n] as uint8 (values 1..102 fit). 1MB scratch, L2-resident.
__device__ uint8_t g_bins[BB * NN];

__global__ void __launch_bounds__(128)
bins_kernel(const float* __restrict__ trace,
            const float* __restrict__ center) {
    const int idx = blockIdx.x * 128 + threadIdx.x;  // (b*128 + f), 0..131071
    const float tv = __ldg(&trace[idx]);

    uint32_t lo = 0, hi = 0;
#pragma unroll
    for (int c = 0; c < CC; c++) {
        float tm = 2.5f * fabsf(tv - __ldg(&center[c]));  // SCALING*|diff|
        if (tm > 10.0f) tm = 10.1f;                       // cutoff -> T+DT
        // bin = trunc(times/DT + 1), IEEE f32 divide (match XLA div.rn)
        uint32_t bin = (uint32_t)(int)(__fdiv_rn(tm, 0.1f) + 1.0f);
        if (c < 4) lo |= bin << (8 * c);
        else       hi |= bin << (8 * (c - 4));
    }
    reinterpret_cast<uint2*>(g_bins)[idx] = make_uint2(lo, hi);
}

__global__ void __launch_bounds__(256, 8)
spike_write_kernel(float* __restrict__ out) {
    const int b   = blockIdx.x & (BB - 1);   // 0..1023 (fast-varying)
    const int tc  = blockIdx.x >> 10;        // 0..19   t-chunk
    const int tid = threadIdx.x;             // 0..255
    const int n0  = tid << 2;                // 4 consecutive n per thread

    // bins for n0..n0+3 in one 32-bit L2-hit load
    const uint32_t packed =
        reinterpret_cast<const uint32_t*>(g_bins)[b * (NN / 4) + tid];
    const int b0 =  packed        & 0xFF;
    const int b1 = (packed >> 8)  & 0xFF;
    const int b2 = (packed >> 16) & 0xFF;
    const int b3 = (packed >> 24);

    const size_t stride4 = (size_t)BB * NN / 4;    // 262144 float4 per t-slab
    float4* outp = reinterpret_cast<float4*>(out + (size_t)b * NN + n0)
                 + (size_t)(tc * TCH) * stride4;

    const int tbase = tc * TCH;
#pragma unroll
    for (int i = 0; i < TCH; i++) {
        const int t = tbase + i;
        float4 v;
        v.x = (b0 == t) ? 1.0f : 0.0f;
        v.y = (b1 == t) ? 1.0f : 0.0f;
        v.z = (b2 == t) ? 1.0f : 0.0f;
        v.w = (b3 == t) ? 1.0f : 0.0f;
        __stcs(outp + (size_t)i * stride4, v);   // streaming store
    }
}

extern "C" void kernel_launch(void* const* d_in, const int* in_sizes, int n_in,
                              void* d_out, int out_size) {
    // Identify inputs by element count — robust to metadata ordering.
    const float* trace  = nullptr;
    const float* center = nullptr;
    for (int i = 0; i < n_in; i++) {
        if (in_sizes[i] == BB * FF)     trace  = (const float*)d_in[i];
        else if (in_sizes[i] == CC)     center = (const float*)d_in[i];
    }
    if (!trace)  trace  = (const float*)d_in[0];
    if (!center) center = (const float*)d_in[1];

    float* out = (float*)d_out;  // [100, 1024, 1024] f32 one-hot

    bins_kernel<<<BB, 128>>>(trace, center);
    spike_write_kernel<<<BB * NCH, 256>>>(out);
}

// round 7
// speedup vs baseline: 1.0414x; 1.0414x over previous
#include <cuda_runtime.h>
#include <cstdint>

// Spike-latency encoder:
//   trace:  [B=1024, F=128] f32,  center: [C=8] f32
//   out:    [T=100, B=1024, N=F*C=1024] f32 one-hot along T per (b,n)
//
// out[t,b,f*8+c] = (bin(b,f,c) == t) ? 1.0f : 0.0f
//   bin = trunc( sel(2.5*|trace[b,f]-center[c]|) / 0.1 + 1 )
//   sel(x) = (x > 10.0f) ? 10.1f : x     (bin -> 102, never matches)
//
// 419 MB pure write stream; measured write ceiling ~6.2 TB/s (R3-R6 sweep).
// R7: single fused kernel, 20-way t-split (R6 write-kernel shape, no extra
// launch). Per-CTA prologue recomputes 4 bins — latency-hidden at occ~82%.

#define BB 1024
#define FF 128
#define CC 8
#define NN 1024
#define TT 100
#define NCH 20          // t-chunks
#define TCH 5           // t-slabs per chunk

__global__ void __launch_bounds__(256, 8)
spike_latency_kernel(const float* __restrict__ trace,
                     const float* __restrict__ center,
                     float* __restrict__ out) {
    const int b   = blockIdx.x & (BB - 1);   // 0..1023 (fast-varying)
    const int tc  = blockIdx.x >> 10;        // 0..19   t-chunk
    const int tid = threadIdx.x;             // 0..255
    const int n0  = tid << 2;                // 4 consecutive n per thread
    const int f   = n0 >> 3;                 // all 4 n share one feature
    const int c0  = n0 & 7;                  // 0 or 4

    const float tv = __ldg(&trace[b * FF + f]);

    int bins[4];
#pragma unroll
    for (int j = 0; j < 4; j++) {
        float ct = __ldg(&center[c0 + j]);
        float tm = 2.5f * fabsf(tv - ct);          // SCALING * |diff|  (f32)
        if (tm > 10.0f) tm = 10.1f;                // cutoff -> TIME_LENGTH + DT
        // bins = trunc(times/DT + 1), IEEE f32 divide (must match XLA div.rn
        // bit-exactly: one flipped bin alone exceeds the 1e-3 rel_err budget)
        bins[j] = (int)(__fdiv_rn(tm, 0.1f) + 1.0f);
    }

    const size_t stride4 = (size_t)BB * NN / 4;    // 262144 float4 per t-slab
    float4* outp = reinterpret_cast<float4*>(out + (size_t)b * NN + n0)
                 + (size_t)(tc * TCH) * stride4;

    const int tbase = tc * TCH;
#pragma unroll
    for (int i = 0; i < TCH; i++) {
        const int t = tbase + i;
        float4 v;
        v.x = (bins[0] == t) ? 1.0f : 0.0f;
        v.y = (bins[1] == t) ? 1.0f : 0.0f;
        v.z = (bins[2] == t) ? 1.0f : 0.0f;
        v.w = (bins[3] == t) ? 1.0f : 0.0f;
        __stcs(outp + (size_t)i * stride4, v);     // streaming store
    }
}

extern "C" void kernel_launch(void* const* d_in, const int* in_sizes, int n_in,
                              void* d_out, int out_size) {
    // Identify inputs by element count — robust to metadata ordering:
    //   trace: 131072 floats, center: 8 floats, dummies: 1 each
    const float* trace  = nullptr;
    const float* center = nullptr;
    for (int i = 0; i < n_in; i++) {
        if (in_sizes[i] == BB * FF)     trace  = (const float*)d_in[i];
        else if (in_sizes[i] == CC)     center = (const float*)d_in[i];
    }
    if (!trace)  trace  = (const float*)d_in[0];
    if (!center) center = (const float*)d_in[1];

    float* out = (float*)d_out;  // [100, 1024, 1024] f32 one-hot

    spike_latency_kernel<<<BB * NCH, 256>>>(trace, center, out);
}